// round 1
// baseline (speedup 1.0000x reference)
#include <cuda_runtime.h>
#include <cuda_bf16.h>
#include <mma.h>

using namespace nvcuda;

// Problem constants (derived generically where cheap)
#define HDIM 512          // H
#define EDIM 128          // E
#define KTOT 640          // H + E
#define MPAD 64           // group rows padded (real = 50)
#define NTILE 128         // N tile per pass (4 passes over 512)
#define KCHUNK 32         // K chunk staged in smem
#define A_STRIDE 648      // 640 + 8 pad (multiple of 4 for wmma ldm)
#define B_STRIDE 132      // 128 + 4 pad
#define THREADS 512       // 16 warps

// Smem layout (floats):
//   As: [MPAD][A_STRIDE]    resident A tile (tf32-converted)
//   Bs: [KCHUNK][B_STRIDE]  staged Wm chunk (tf32-converted)
//   Cs: [MPAD][B_STRIDE]    accum spill for epilogue
#define SMEM_FLOATS (MPAD * A_STRIDE + KCHUNK * B_STRIDE + MPAD * B_STRIDE)
#define SMEM_BYTES (SMEM_FLOATS * sizeof(float))

__global__ __launch_bounds__(THREADS, 1)
void pool_hidden_kernel(const float* __restrict__ hist_enc,
                        const float* __restrict__ hist_pos,
                        const int*   __restrict__ sse,
                        const float* __restrict__ Ws,
                        const float* __restrict__ bs,
                        const float* __restrict__ Wm,
                        const float* __restrict__ bm,
                        float* __restrict__ out)
{
    extern __shared__ float smem[];
    float* As = smem;
    float* Bs = As + MPAD * A_STRIDE;
    float* Cs = Bs + KCHUNK * B_STRIDE;

    const int g     = blockIdx.x;
    const int tid   = threadIdx.x;
    const int start = sse[g];
    const int end   = sse[g + 1];
    const int cnt   = end - start;        // 50 for this dataset, <= MPAD assumed

    // Anchor position (first row of group)
    const float ax = hist_pos[2 * start + 0];
    const float ay = hist_pos[2 * start + 1];

    // ---- Build resident A tile -------------------------------------------
    // Cols [0, 512): hist_enc rows of this group, converted to tf32.
    for (int idx = tid; idx < cnt * (HDIM / 4); idx += THREADS) {
        const int m  = idx / (HDIM / 4);
        const int c4 = idx % (HDIM / 4);
        const float4 v = reinterpret_cast<const float4*>(
            hist_enc + (size_t)(start + m) * HDIM)[c4];
        float* dst = As + m * A_STRIDE + c4 * 4;
        dst[0] = wmma::__float_to_tf32(v.x);
        dst[1] = wmma::__float_to_tf32(v.y);
        dst[2] = wmma::__float_to_tf32(v.z);
        dst[3] = wmma::__float_to_tf32(v.w);
    }
    // Cols [512, 640): emb = relu(rel @ Ws + bs), computed on the fly.
    for (int idx = tid; idx < cnt * EDIM; idx += THREADS) {
        const int m = idx / EDIM;
        const int e = idx % EDIM;
        const float rx = hist_pos[2 * (start + m) + 0] - ax;
        const float ry = hist_pos[2 * (start + m) + 1] - ay;
        float v = fmaf(rx, Ws[e], fmaf(ry, Ws[EDIM + e], bs[e]));
        v = fmaxf(v, 0.0f);
        As[m * A_STRIDE + HDIM + e] = wmma::__float_to_tf32(v);
    }
    // Zero pad rows [cnt, MPAD)
    for (int idx = tid; idx < (MPAD - cnt) * KTOT; idx += THREADS) {
        const int m = cnt + idx / KTOT;
        const int c = idx % KTOT;
        As[m * A_STRIDE + c] = 0.0f;
    }
    __syncthreads();

    // Warp tiling: 16 warps -> 4x4 grid over [64 x 128] output tile.
    const int warp = tid / 32;
    const int wm   = warp / 4;   // m offset = 16*wm
    const int wn   = warp % 4;   // n offset = 32*wn (two 16-wide frags)

    for (int n0 = 0; n0 < HDIM; n0 += NTILE) {
        wmma::fragment<wmma::accumulator, 16, 16, 8, float> acc0, acc1;
        wmma::fill_fragment(acc0, 0.0f);
        wmma::fill_fragment(acc1, 0.0f);

        for (int k0 = 0; k0 < KTOT; k0 += KCHUNK) {
            __syncthreads();   // Bs (and Cs of previous pass) free to overwrite
            // Stage Wm[k0:k0+32, n0:n0+128] -> Bs (tf32)
            for (int idx = tid; idx < KCHUNK * (NTILE / 4); idx += THREADS) {
                const int r  = idx / (NTILE / 4);
                const int c4 = idx % (NTILE / 4);
                const float4 v = reinterpret_cast<const float4*>(
                    Wm + (size_t)(k0 + r) * HDIM + n0)[c4];
                float* dst = Bs + r * B_STRIDE + c4 * 4;
                dst[0] = wmma::__float_to_tf32(v.x);
                dst[1] = wmma::__float_to_tf32(v.y);
                dst[2] = wmma::__float_to_tf32(v.z);
                dst[3] = wmma::__float_to_tf32(v.w);
            }
            __syncthreads();

            #pragma unroll
            for (int kk = 0; kk < KCHUNK; kk += 8) {
                wmma::fragment<wmma::matrix_a, 16, 16, 8,
                               wmma::precision::tf32, wmma::row_major> fa;
                wmma::load_matrix_sync(fa, As + (16 * wm) * A_STRIDE + k0 + kk,
                                       A_STRIDE);
                wmma::fragment<wmma::matrix_b, 16, 16, 8,
                               wmma::precision::tf32, wmma::row_major> fb0, fb1;
                wmma::load_matrix_sync(fb0, Bs + kk * B_STRIDE + 32 * wn,
                                       B_STRIDE);
                wmma::load_matrix_sync(fb1, Bs + kk * B_STRIDE + 32 * wn + 16,
                                       B_STRIDE);
                wmma::mma_sync(acc0, fa, fb0, acc0);
                wmma::mma_sync(acc1, fa, fb1, acc1);
            }
        }

        __syncthreads();   // everyone done reading Bs/Cs before Cs overwrite
        wmma::store_matrix_sync(Cs + (16 * wm) * B_STRIDE + 32 * wn, acc0,
                                B_STRIDE, wmma::mem_row_major);
        wmma::store_matrix_sync(Cs + (16 * wm) * B_STRIDE + 32 * wn + 16, acc1,
                                B_STRIDE, wmma::mem_row_major);
        __syncthreads();

        // Epilogue: per-column max over the cnt real rows, then relu(max + b).
        // Valid because x -> relu(x + b) is monotone nondecreasing.
        if (tid < NTILE) {
            float mv = Cs[tid];
            #pragma unroll 5
            for (int m = 1; m < cnt; m++)
                mv = fmaxf(mv, Cs[m * B_STRIDE + tid]);
            out[(size_t)g * HDIM + n0 + tid] = fmaxf(mv + bm[n0 + tid], 0.0f);
        }
        // Next pass's first inner __syncthreads orders epilogue reads before
        // any Bs/Cs overwrite.
    }
}

extern "C" void kernel_launch(void* const* d_in, const int* in_sizes, int n_in,
                              void* d_out, int out_size)
{
    const float* hist_enc = (const float*)d_in[0];
    const float* hist_pos = (const float*)d_in[1];
    const int*   sse      = (const int*)d_in[2];
    const float* Ws       = (const float*)d_in[3];
    const float* bs       = (const float*)d_in[4];
    const float* Wm       = (const float*)d_in[5];
    const float* bm       = (const float*)d_in[6];
    float* out            = (float*)d_out;

    const int num_groups = in_sizes[2] - 1;

    // Idempotent, capture-safe (no stream work, no allocation).
    cudaFuncSetAttribute(pool_hidden_kernel,
                         cudaFuncAttributeMaxDynamicSharedMemorySize,
                         (int)SMEM_BYTES);

    pool_hidden_kernel<<<num_groups, THREADS, SMEM_BYTES>>>(
        hist_enc, hist_pos, sse, Ws, bs, Wm, bm, out);
}

// round 3
// speedup vs baseline: 1.3421x; 1.3421x over previous
#include <cuda_runtime.h>
#include <cuda_bf16.h>
#include <mma.h>

using namespace nvcuda;

#define HDIM 512
#define EDIM 128
#define KTOT 640
#define MPAD 64            // one group (<=64 rows) per CTA
#define KC 16              // K chunk staged for B
#define A_STRIDE 648       // floats, 8-bank shift per row
#define B_STRIDE 520       // floats, 8-bank shift per row
#define S_STRIDE 36        // epilogue strip stride (floats)
#define THREADS 512        // 16 warps, warp w owns cols [32w, 32w+32)

// Smem: A resident [64][A_STRIDE] tf32, B chunk [KC][B_STRIDE] tf32.
// Epilogue strips (16 x [64][S_STRIDE]) reuse the A region.
#define SMEM_FLOATS (MPAD * A_STRIDE + KC * B_STRIDE)
#define SMEM_BYTES  (SMEM_FLOATS * sizeof(float))

__global__ __launch_bounds__(THREADS, 1)
void pool_hidden_kernel(const float* __restrict__ hist_enc,
                        const float* __restrict__ hist_pos,
                        const int*   __restrict__ sse,
                        const float* __restrict__ Ws,
                        const float* __restrict__ bs,
                        const float* __restrict__ Wm,
                        const float* __restrict__ bm,
                        float* __restrict__ out)
{
    extern __shared__ float smem[];
    float* As = smem;
    float* Bs = As + MPAD * A_STRIDE;

    const int g     = blockIdx.x;
    const int tid   = threadIdx.x;
    const int wid   = tid >> 5;
    const int start = sse[g];
    const int cnt   = sse[g + 1] - start;      // <= MPAD

    const float ax = hist_pos[2 * start + 0];
    const float ay = hist_pos[2 * start + 1];

    // ---- Build resident A tile (tf32) ------------------------------------
    for (int idx = tid; idx < cnt * (HDIM / 4); idx += THREADS) {
        const int m  = idx / (HDIM / 4);
        const int c4 = idx % (HDIM / 4);
        const float4 v = reinterpret_cast<const float4*>(
            hist_enc + (size_t)(start + m) * HDIM)[c4];
        float* dst = As + m * A_STRIDE + c4 * 4;
        dst[0] = wmma::__float_to_tf32(v.x);
        dst[1] = wmma::__float_to_tf32(v.y);
        dst[2] = wmma::__float_to_tf32(v.z);
        dst[3] = wmma::__float_to_tf32(v.w);
    }
    for (int idx = tid; idx < cnt * EDIM; idx += THREADS) {
        const int m = idx / EDIM;
        const int e = idx % EDIM;
        const float rx = hist_pos[2 * (start + m) + 0] - ax;
        const float ry = hist_pos[2 * (start + m) + 1] - ay;
        float v = fmaxf(fmaf(rx, Ws[e], fmaf(ry, Ws[EDIM + e], bs[e])), 0.0f);
        As[m * A_STRIDE + HDIM + e] = wmma::__float_to_tf32(v);
    }
    for (int idx = tid; idx < (MPAD - cnt) * KTOT; idx += THREADS) {
        const int m = cnt + idx / KTOT;
        const int c = idx % KTOT;
        As[m * A_STRIDE + c] = 0.0f;
    }

    // ---- Mainloop: persistent 64x512 accumulators, stream B in KC chunks --
    wmma::fragment<wmma::accumulator, 16, 16, 8, float> acc[4][2];
    #pragma unroll
    for (int i = 0; i < 4; i++) {
        wmma::fill_fragment(acc[i][0], 0.0f);
        wmma::fill_fragment(acc[i][1], 0.0f);
    }

    for (int k0 = 0; k0 < KTOT; k0 += KC) {
        __syncthreads();   // A visible (first iter); Bs readers done (later iters)
        // Stage Wm[k0:k0+KC, 0:512] -> Bs (tf32), coalesced
        for (int idx = tid; idx < KC * (HDIM / 4); idx += THREADS) {
            const int r  = idx / (HDIM / 4);
            const int c4 = idx % (HDIM / 4);
            const float4 v = reinterpret_cast<const float4*>(
                Wm + (size_t)(k0 + r) * HDIM)[c4];
            float* dst = Bs + r * B_STRIDE + c4 * 4;
            dst[0] = wmma::__float_to_tf32(v.x);
            dst[1] = wmma::__float_to_tf32(v.y);
            dst[2] = wmma::__float_to_tf32(v.z);
            dst[3] = wmma::__float_to_tf32(v.w);
        }
        __syncthreads();

        #pragma unroll
        for (int kk = 0; kk < KC; kk += 8) {
            wmma::fragment<wmma::matrix_a, 16, 16, 8,
                           wmma::precision::tf32, wmma::row_major> fa[4];
            #pragma unroll
            for (int i = 0; i < 4; i++)
                wmma::load_matrix_sync(fa[i], As + 16 * i * A_STRIDE + k0 + kk,
                                       A_STRIDE);
            #pragma unroll
            for (int j = 0; j < 2; j++) {
                wmma::fragment<wmma::matrix_b, 16, 16, 8,
                               wmma::precision::tf32, wmma::row_major> fb;
                wmma::load_matrix_sync(fb, Bs + kk * B_STRIDE + 32 * wid + 16 * j,
                                       B_STRIDE);
                #pragma unroll
                for (int i = 0; i < 4; i++)
                    wmma::mma_sync(acc[i][j], fa[i], fb, acc[i][j]);
            }
        }
    }

    // ---- Epilogue: per-warp column strip, max over cnt rows, relu(+bm) ----
    __syncthreads();   // all warps done reading As before strips overwrite it
    float* strip = smem + wid * (MPAD * S_STRIDE);
    #pragma unroll
    for (int i = 0; i < 4; i++) {
        wmma::store_matrix_sync(strip + 16 * i * S_STRIDE, acc[i][0],
                                S_STRIDE, wmma::mem_row_major);
        wmma::store_matrix_sync(strip + 16 * i * S_STRIDE + 16, acc[i][1],
                                S_STRIDE, wmma::mem_row_major);
    }
    __syncthreads();

    {
        const int w = tid >> 5;          // strip index
        const int c = tid & 31;          // column within strip
        const float* s = smem + w * (MPAD * S_STRIDE) + c;
        float m0 = s[0];
        float m1 = -3.4e38f, m2 = -3.4e38f, m3 = -3.4e38f;
        int r = 1;
        for (; r + 3 < cnt; r += 4) {
            m0 = fmaxf(m0, s[(r + 0) * S_STRIDE]);
            m1 = fmaxf(m1, s[(r + 1) * S_STRIDE]);
            m2 = fmaxf(m2, s[(r + 2) * S_STRIDE]);
            m3 = fmaxf(m3, s[(r + 3) * S_STRIDE]);
        }
        for (; r < cnt; r++)
            m0 = fmaxf(m0, s[r * S_STRIDE]);
        float mv = fmaxf(fmaxf(m0, m1), fmaxf(m2, m3));
        const int col = 32 * w + c;
        out[(size_t)g * HDIM + col] = fmaxf(mv + bm[col], 0.0f);
    }
}

extern "C" void kernel_launch(void* const* d_in, const int* in_sizes, int n_in,
                              void* d_out, int out_size)
{
    const float* hist_enc = (const float*)d_in[0];
    const float* hist_pos = (const float*)d_in[1];
    const int*   sse      = (const int*)d_in[2];
    const float* Ws       = (const float*)d_in[3];
    const float* bs       = (const float*)d_in[4];
    const float* Wm       = (const float*)d_in[5];
    const float* bm       = (const float*)d_in[6];
    float* out            = (float*)d_out;

    const int num_groups = in_sizes[2] - 1;

    cudaFuncSetAttribute(pool_hidden_kernel,
                         cudaFuncAttributeMaxDynamicSharedMemorySize,
                         (int)SMEM_BYTES);

    pool_hidden_kernel<<<num_groups, THREADS, SMEM_BYTES>>>(
        hist_enc, hist_pos, sse, Ws, bs, Wm, bm, out);
}

// round 6
// speedup vs baseline: 1.7019x; 1.2681x over previous
#include <cuda_runtime.h>
#include <cuda_bf16.h>
#include <mma.h>

using namespace nvcuda;

#define HDIM 512
#define EDIM 128
#define KTOT 640
#define MPAD 64          // one group (<=64 rows) per CTA
#define KC 16            // K chunk
#define NCH (KTOT / KC)  // 40 chunks
#define NP 256           // N columns per pass (2 passes)
#define A_ST 20          // A chunk row stride (floats): 16 + 4
#define B_ST 264         // B chunk row stride (floats): 256 + 8
#define S_ST 36          // epilogue strip stride (floats)
#define THREADS 256      // 8 warps; warp w owns cols [32w, 32w+32) of the pass

// Mainloop smem: As[2][64][A_ST] + Bs[2][KC][B_ST] = 2560 + 8448 floats = 44 KB
// Epilogue strips: 8 x [64][S_ST] = 18432 floats = 73.7 KB (reuses same region)
#define SM_B_OFF (2 * MPAD * A_ST)
#define SMEM_FLOATS (8 * MPAD * S_ST)      // 18432 (epilogue is the max)
#define SMEM_BYTES (SMEM_FLOATS * sizeof(float))

__global__ __launch_bounds__(THREADS, 2)
void pool_hidden_kernel(const float* __restrict__ hist_enc,
                        const float* __restrict__ hist_pos,
                        const int*   __restrict__ sse,
                        const float* __restrict__ Ws,
                        const float* __restrict__ bs,
                        const float* __restrict__ Wm,
                        const float* __restrict__ bm,
                        float* __restrict__ out)
{
    extern __shared__ float smem[];
    float* As = smem;                // [buf][64][A_ST]
    float* Bs = smem + SM_B_OFF;     // [buf][KC][B_ST]

    const int g     = blockIdx.x;
    const int tid   = threadIdx.x;
    const int wid   = tid >> 5;
    const int start = sse[g];
    const int cnt   = sse[g + 1] - start;      // <= MPAD

    const float ax = hist_pos[2 * start + 0];
    const float ay = hist_pos[2 * start + 1];

    // Staging thread map (fixed per thread):
    //  A: 64 rows x 4 float4  -> ar = tid>>2, ac4 = tid&3  (1 float4/thread)
    //  B: KC rows x 64 float4 -> 4 float4/thread: flat = tid + 256*j
    const int ar  = tid >> 2;
    const int ac4 = tid & 3;

    for (int pass = 0; pass < 2; pass++) {
        const int n0 = pass * NP;

        wmma::fragment<wmma::accumulator, 16, 16, 8, float> acc[4][2];
        #pragma unroll
        for (int i = 0; i < 4; i++) {
            wmma::fill_fragment(acc[i][0], 0.0f);
            wmma::fill_fragment(acc[i][1], 0.0f);
        }

        // ---- load chunk into registers (tf32-converted) -------------------
        float4 areg;
        float4 breg[4];
        auto load_chunk = [&](int k0) {
            // A: rows [0,cnt) from hist_enc / emb, pad rows zero
            float4 v = make_float4(0.f, 0.f, 0.f, 0.f);
            if (ar < cnt) {
                if (k0 < HDIM) {
                    v = *(const float4*)(hist_enc +
                        (size_t)(start + ar) * HDIM + k0 + 4 * ac4);
                } else {
                    const float rx = hist_pos[2 * (start + ar) + 0] - ax;
                    const float ry = hist_pos[2 * (start + ar) + 1] - ay;
                    const int e = k0 - HDIM + 4 * ac4;
                    v.x = fmaxf(fmaf(rx, Ws[e+0], fmaf(ry, Ws[EDIM+e+0], bs[e+0])), 0.f);
                    v.y = fmaxf(fmaf(rx, Ws[e+1], fmaf(ry, Ws[EDIM+e+1], bs[e+1])), 0.f);
                    v.z = fmaxf(fmaf(rx, Ws[e+2], fmaf(ry, Ws[EDIM+e+2], bs[e+2])), 0.f);
                    v.w = fmaxf(fmaf(rx, Ws[e+3], fmaf(ry, Ws[EDIM+e+3], bs[e+3])), 0.f);
                }
            }
            areg.x = wmma::__float_to_tf32(v.x);
            areg.y = wmma::__float_to_tf32(v.y);
            areg.z = wmma::__float_to_tf32(v.z);
            areg.w = wmma::__float_to_tf32(v.w);
            // B: Wm[k0+r][n0+c]
            #pragma unroll
            for (int j = 0; j < 4; j++) {
                const int flat = tid + THREADS * j;
                const int r  = flat >> 6;
                const int c4 = flat & 63;
                const float4 b = *(const float4*)(Wm +
                    (size_t)(k0 + r) * HDIM + n0 + 4 * c4);
                breg[j].x = wmma::__float_to_tf32(b.x);
                breg[j].y = wmma::__float_to_tf32(b.y);
                breg[j].z = wmma::__float_to_tf32(b.z);
                breg[j].w = wmma::__float_to_tf32(b.w);
            }
        };
        auto store_chunk = [&](int buf) {
            *(float4*)(As + buf * MPAD * A_ST + ar * A_ST + 4 * ac4) = areg;
            #pragma unroll
            for (int j = 0; j < 4; j++) {
                const int flat = tid + THREADS * j;
                const int r  = flat >> 6;
                const int c4 = flat & 63;
                *(float4*)(Bs + buf * KC * B_ST + r * B_ST + 4 * c4) = breg[j];
            }
        };

        // Prologue: chunk 0 -> buf 0
        load_chunk(0);
        store_chunk(0);

        for (int i = 0; i < NCH; i++) {
            const int buf = i & 1;
            if (i + 1 < NCH)
                load_chunk((i + 1) * KC);
            __syncthreads();   // chunk i visible; buf (i+1)&1 readers done
            // ---- mma on chunk i ----
            const float* Ab = As + buf * MPAD * A_ST;
            const float* Bb = Bs + buf * KC * B_ST;
            #pragma unroll
            for (int kk = 0; kk < KC; kk += 8) {
                wmma::fragment<wmma::matrix_a, 16, 16, 8,
                               wmma::precision::tf32, wmma::row_major> fa[4];
                #pragma unroll
                for (int i2 = 0; i2 < 4; i2++)
                    wmma::load_matrix_sync(fa[i2], Ab + 16 * i2 * A_ST + kk, A_ST);
                #pragma unroll
                for (int j = 0; j < 2; j++) {
                    wmma::fragment<wmma::matrix_b, 16, 16, 8,
                                   wmma::precision::tf32, wmma::row_major> fb;
                    wmma::load_matrix_sync(fb, Bb + kk * B_ST + 32 * wid + 16 * j,
                                           B_ST);
                    #pragma unroll
                    for (int i2 = 0; i2 < 4; i2++)
                        wmma::mma_sync(acc[i2][j], fa[i2], fb, acc[i2][j]);
                }
            }
            if (i + 1 < NCH)
                store_chunk((i + 1) & 1);
        }

        // ---- epilogue: strips in smem, column max, relu(+bm) --------------
        __syncthreads();   // all warps done with mainloop smem
        float* strip = smem + wid * (MPAD * S_ST);
        #pragma unroll
        for (int i = 0; i < 4; i++) {
            wmma::store_matrix_sync(strip + 16 * i * S_ST, acc[i][0],
                                    S_ST, wmma::mem_row_major);
            wmma::store_matrix_sync(strip + 16 * i * S_ST + 16, acc[i][1],
                                    S_ST, wmma::mem_row_major);
        }
        __syncthreads();
        {
            const int w = tid >> 5;
            const int c = tid & 31;
            const float* s = smem + w * (MPAD * S_ST) + c;
            float m0 = s[0];
            float m1 = -3.4e38f, m2 = -3.4e38f, m3 = -3.4e38f;
            int r = 1;
            for (; r + 3 < cnt; r += 4) {
                m0 = fmaxf(m0, s[(r + 0) * S_ST]);
                m1 = fmaxf(m1, s[(r + 1) * S_ST]);
                m2 = fmaxf(m2, s[(r + 2) * S_ST]);
                m3 = fmaxf(m3, s[(r + 3) * S_ST]);
            }
            for (; r < cnt; r++)
                m0 = fmaxf(m0, s[r * S_ST]);
            const float mv = fmaxf(fmaxf(m0, m1), fmaxf(m2, m3));
            const int col = n0 + 32 * w + c;
            out[(size_t)g * HDIM + col] = fmaxf(mv + bm[col], 0.0f);
        }
        __syncthreads();   // strips read before next pass restages smem
    }
}

extern "C" void kernel_launch(void* const* d_in, const int* in_sizes, int n_in,
                              void* d_out, int out_size)
{
    const float* hist_enc = (const float*)d_in[0];
    const float* hist_pos = (const float*)d_in[1];
    const int*   sse      = (const int*)d_in[2];
    const float* Ws       = (const float*)d_in[3];
    const float* bs       = (const float*)d_in[4];
    const float* Wm       = (const float*)d_in[5];
    const float* bm       = (const float*)d_in[6];
    float* out            = (float*)d_out;

    const int num_groups = in_sizes[2] - 1;

    cudaFuncSetAttribute(pool_hidden_kernel,
                         cudaFuncAttributeMaxDynamicSharedMemorySize,
                         (int)SMEM_BYTES);

    pool_hidden_kernel<<<num_groups, THREADS, SMEM_BYTES>>>(
        hist_enc, hist_pos, sse, Ws, bs, Wm, bm, out);
}

// round 7
// speedup vs baseline: 1.7553x; 1.0314x over previous
#include <cuda_runtime.h>
#include <cuda_bf16.h>
#include <mma.h>
#include <cstdint>

using namespace nvcuda;

#define HDIM 512
#define EDIM 128
#define KTOT 640
#define MPAD 64          // one group (<=64 rows) per CTA
#define KC 32            // K chunk
#define NCH (KTOT / KC)  // 20 chunks
#define NP 256           // N columns per pass (2 passes)
#define A_ST 36          // A chunk row stride (floats): 32 + 4
#define B_ST 264         // B chunk row stride (floats): 256 + 8
#define S_ST 36          // epilogue strip stride (floats)
#define THREADS 256      // 8 warps; warp w owns cols [32w, 32w+32) of the pass

// Smem (floats): As[2][64][A_ST] = 4608, Bs[2][KC][B_ST] = 16896 -> 21504 fl = 86 KB
// Epilogue strips: 8 x [64][S_ST] = 18432 floats (reuses same region)
#define SM_B_OFF (2 * MPAD * A_ST)
#define SMEM_FLOATS (SM_B_OFF + 2 * KC * B_ST)
#define SMEM_BYTES (SMEM_FLOATS * sizeof(float))

__device__ __forceinline__ uint32_t smem_u32(const void* p) {
    uint32_t a;
    asm("{ .reg .u64 t; cvta.to.shared.u64 t, %1; cvt.u32.u64 %0, t; }" : "=r"(a) : "l"(p));
    return a;
}
__device__ __forceinline__ void cp_async16(uint32_t saddr, const void* gptr) {
    asm volatile("cp.async.cg.shared.global [%0], [%1], 16;" :: "r"(saddr), "l"(gptr));
}
#define CP_COMMIT() asm volatile("cp.async.commit_group;" ::: "memory")
#define CP_WAIT0()  asm volatile("cp.async.wait_group 0;" ::: "memory")

__global__ __launch_bounds__(THREADS, 2)
void pool_hidden_kernel(const float* __restrict__ hist_enc,
                        const float* __restrict__ hist_pos,
                        const int*   __restrict__ sse,
                        const float* __restrict__ Ws,
                        const float* __restrict__ bs,
                        const float* __restrict__ Wm,
                        const float* __restrict__ bm,
                        float* __restrict__ out)
{
    extern __shared__ float smem[];
    float* As = smem;                // [buf][64][A_ST]
    float* Bs = smem + SM_B_OFF;     // [buf][KC][B_ST]

    const int g     = blockIdx.x;
    const int tid   = threadIdx.x;
    const int wid   = tid >> 5;
    const int start = sse[g];
    const int cnt   = sse[g + 1] - start;      // <= MPAD

    const float ax = hist_pos[2 * start + 0];
    const float ay = hist_pos[2 * start + 1];

    // A staging map: 64 rows x 8 float4 per chunk -> 2 float4/thread
    //   q in {0,1}: flat = tid + 256*q, ar = flat>>3, ac4 = flat&7
    // B staging map: KC rows x 64 float4 -> 8 float4/thread (cp.async)
    //   j in 0..7:  flat = tid + 256*j, br = flat>>6, bc4 = flat&63

    // ---- A chunk loader: global/emb -> regs (tf32 RN for A) --------------
    float4 areg[2];
    auto load_A = [&](int k0) {
        #pragma unroll
        for (int q = 0; q < 2; q++) {
            const int flat = tid + THREADS * q;
            const int r   = flat >> 3;
            const int c4  = flat & 7;
            float4 v = make_float4(0.f, 0.f, 0.f, 0.f);
            if (r < cnt) {
                const int kcol = k0 + 4 * c4;
                if (kcol < HDIM) {
                    v = *(const float4*)(hist_enc +
                        (size_t)(start + r) * HDIM + kcol);
                } else {
                    const float rx = hist_pos[2 * (start + r) + 0] - ax;
                    const float ry = hist_pos[2 * (start + r) + 1] - ay;
                    const int e = kcol - HDIM;
                    v.x = fmaxf(fmaf(rx, Ws[e+0], fmaf(ry, Ws[EDIM+e+0], bs[e+0])), 0.f);
                    v.y = fmaxf(fmaf(rx, Ws[e+1], fmaf(ry, Ws[EDIM+e+1], bs[e+1])), 0.f);
                    v.z = fmaxf(fmaf(rx, Ws[e+2], fmaf(ry, Ws[EDIM+e+2], bs[e+2])), 0.f);
                    v.w = fmaxf(fmaf(rx, Ws[e+3], fmaf(ry, Ws[EDIM+e+3], bs[e+3])), 0.f);
                }
            }
            areg[q].x = wmma::__float_to_tf32(v.x);
            areg[q].y = wmma::__float_to_tf32(v.y);
            areg[q].z = wmma::__float_to_tf32(v.z);
            areg[q].w = wmma::__float_to_tf32(v.w);
        }
    };
    auto store_A = [&](int buf) {
        #pragma unroll
        for (int q = 0; q < 2; q++) {
            const int flat = tid + THREADS * q;
            const int r  = flat >> 3;
            const int c4 = flat & 7;
            *(float4*)(As + buf * MPAD * A_ST + r * A_ST + 4 * c4) = areg[q];
        }
    };
    // B chunk: raw fp32 via cp.async (HW-truncated to tf32 by the MMA)
    auto issue_B = [&](int k0, int n0, int buf) {
        const uint32_t sb = smem_u32(Bs + buf * KC * B_ST);
        #pragma unroll
        for (int j = 0; j < 8; j++) {
            const int flat = tid + THREADS * j;
            const int r  = flat >> 6;
            const int c4 = flat & 63;
            cp_async16(sb + (uint32_t)(r * B_ST + 4 * c4) * 4,
                       Wm + (size_t)(k0 + r) * HDIM + n0 + 4 * c4);
        }
        CP_COMMIT();
    };

    for (int pass = 0; pass < 2; pass++) {
        const int n0 = pass * NP;

        wmma::fragment<wmma::accumulator, 16, 16, 8, float> acc[4][2];
        #pragma unroll
        for (int i = 0; i < 4; i++) {
            wmma::fill_fragment(acc[i][0], 0.0f);
            wmma::fill_fragment(acc[i][1], 0.0f);
        }

        // Prologue: A0 + B0 into buf 0
        load_A(0);
        store_A(0);
        issue_B(0, n0, 0);

        for (int i = 0; i < NCH; i++) {
            const int buf = i & 1;
            CP_WAIT0();            // my B(i) copies have landed
            __syncthreads();       // everyone's B(i) + A(i) visible; buf^1 free
            if (i + 1 < NCH) {
                issue_B((i + 1) * KC, n0, buf ^ 1);
                load_A((i + 1) * KC);      // LDG in flight across the mma
            }

            const float* Ab = As + buf * MPAD * A_ST;
            const float* Bb = Bs + buf * KC * B_ST;
            #pragma unroll
            for (int kk = 0; kk < KC; kk += 8) {
                wmma::fragment<wmma::matrix_a, 16, 16, 8,
                               wmma::precision::tf32, wmma::row_major> fa[4];
                #pragma unroll
                for (int i2 = 0; i2 < 4; i2++)
                    wmma::load_matrix_sync(fa[i2], Ab + 16 * i2 * A_ST + kk, A_ST);
                #pragma unroll
                for (int j = 0; j < 2; j++) {
                    wmma::fragment<wmma::matrix_b, 16, 16, 8,
                                   wmma::precision::tf32, wmma::row_major> fb;
                    wmma::load_matrix_sync(fb, Bb + kk * B_ST + 32 * wid + 16 * j,
                                           B_ST);
                    #pragma unroll
                    for (int i2 = 0; i2 < 4; i2++)
                        wmma::mma_sync(acc[i2][j], fa[i2], fb, acc[i2][j]);
                }
            }
            if (i + 1 < NCH)
                store_A(buf ^ 1);
        }

        // ---- epilogue: strips in smem, column max, relu(+bm) --------------
        __syncthreads();
        float* strip = smem + wid * (MPAD * S_ST);
        #pragma unroll
        for (int i = 0; i < 4; i++) {
            wmma::store_matrix_sync(strip + 16 * i * S_ST, acc[i][0],
                                    S_ST, wmma::mem_row_major);
            wmma::store_matrix_sync(strip + 16 * i * S_ST + 16, acc[i][1],
                                    S_ST, wmma::mem_row_major);
        }
        __syncthreads();
        {
            const int w = tid >> 5;
            const int c = tid & 31;
            const float* s = smem + w * (MPAD * S_ST) + c;
            float m0 = s[0];
            float m1 = -3.4e38f, m2 = -3.4e38f, m3 = -3.4e38f;
            int r = 1;
            for (; r + 3 < cnt; r += 4) {
                m0 = fmaxf(m0, s[(r + 0) * S_ST]);
                m1 = fmaxf(m1, s[(r + 1) * S_ST]);
                m2 = fmaxf(m2, s[(r + 2) * S_ST]);
                m3 = fmaxf(m3, s[(r + 3) * S_ST]);
            }
            for (; r < cnt; r++)
                m0 = fmaxf(m0, s[r * S_ST]);
            const float mv = fmaxf(fmaxf(m0, m1), fmaxf(m2, m3));
            const int col = n0 + 32 * w + c;
            out[(size_t)g * HDIM + col] = fmaxf(mv + bm[col], 0.0f);
        }
        __syncthreads();   // strips read before next pass restages smem
    }
}

extern "C" void kernel_launch(void* const* d_in, const int* in_sizes, int n_in,
                              void* d_out, int out_size)
{
    const float* hist_enc = (const float*)d_in[0];
    const float* hist_pos = (const float*)d_in[1];
    const int*   sse      = (const int*)d_in[2];
    const float* Ws       = (const float*)d_in[3];
    const float* bs       = (const float*)d_in[4];
    const float* Wm       = (const float*)d_in[5];
    const float* bm       = (const float*)d_in[6];
    float* out            = (float*)d_out;

    const int num_groups = in_sizes[2] - 1;

    cudaFuncSetAttribute(pool_hidden_kernel,
                         cudaFuncAttributeMaxDynamicSharedMemorySize,
                         (int)SMEM_BYTES);

    pool_hidden_kernel<<<num_groups, THREADS, SMEM_BYTES>>>(
        hist_enc, hist_pos, sse, Ws, bs, Wm, bm, out);
}

// round 8
// speedup vs baseline: 4.5598x; 2.5977x over previous
#include <cuda_runtime.h>
#include <cuda_fp16.h>
#include <mma.h>
#include <cstdint>

using namespace nvcuda;

#define HDIM 512
#define EDIM 128
#define KTOT 640
#define MPAD 64          // one group (<=64 rows) per CTA
#define KC 32            // K chunk
#define NCH (KTOT / KC)  // 20 chunks
#define NP 256           // N columns per pass (2 passes)
#define A_ST 40          // A chunk row stride (halfs): 32 + 8
#define B_ST 264         // B chunk row stride (halfs): 256 + 8
#define S_ST 36          // epilogue strip stride (floats)
#define THREADS 256      // 8 warps; warp w owns cols [32w, 32w+32) of the pass

// Mainloop smem: As[2][64][A_ST] halfs = 10240 B, Bs[2][KC][B_ST] halfs = 33792 B
// Epilogue strips: 8 x [64][S_ST] floats = 73728 B (max; reuses same region)
#define SM_B_OFF_H (2 * MPAD * A_ST)                   // in halfs
#define SMEM_BYTES (8 * MPAD * S_ST * sizeof(float))   // 73728

__global__ __launch_bounds__(THREADS, 2)
void pool_hidden_kernel(const float* __restrict__ hist_enc,
                        const float* __restrict__ hist_pos,
                        const int*   __restrict__ sse,
                        const float* __restrict__ Ws,
                        const float* __restrict__ bs,
                        const float* __restrict__ Wm,
                        const float* __restrict__ bm,
                        float* __restrict__ out)
{
    extern __shared__ float smemf[];
    __half* As = (__half*)smemf;                 // [buf][64][A_ST]
    __half* Bs = (__half*)smemf + SM_B_OFF_H;    // [buf][KC][B_ST]

    const int g     = blockIdx.x;
    const int tid   = threadIdx.x;
    const int wid   = tid >> 5;
    const int start = sse[g];
    const int cnt   = sse[g + 1] - start;        // <= MPAD

    const float ax = hist_pos[2 * start + 0];
    const float ay = hist_pos[2 * start + 1];

    // A map: 64 rows x 4 groups-of-8 cols -> 1 unit/thread: r=tid>>2, c8=tid&3
    // B map: KC rows x 32 groups-of-8 cols = 1024 units -> 4/thread
    const int ar  = tid >> 2;
    const int ac8 = tid & 3;

    // ---- A chunk: global/emb -> regs (RN fp16) ---------------------------
    uint4 areg;
    auto load_A = [&](int k0) {
        float v[8];
        #pragma unroll
        for (int t = 0; t < 8; t++) v[t] = 0.f;
        if (ar < cnt) {
            const int kcol = k0 + 8 * ac8;
            if (kcol < HDIM) {
                const float4 p0 = *(const float4*)(hist_enc +
                    (size_t)(start + ar) * HDIM + kcol);
                const float4 p1 = *(const float4*)(hist_enc +
                    (size_t)(start + ar) * HDIM + kcol + 4);
                v[0]=p0.x; v[1]=p0.y; v[2]=p0.z; v[3]=p0.w;
                v[4]=p1.x; v[5]=p1.y; v[6]=p1.z; v[7]=p1.w;
            } else {
                const float rx = hist_pos[2 * (start + ar) + 0] - ax;
                const float ry = hist_pos[2 * (start + ar) + 1] - ay;
                const int e = kcol - HDIM;
                #pragma unroll
                for (int t = 0; t < 8; t++)
                    v[t] = fmaxf(fmaf(rx, Ws[e + t],
                                 fmaf(ry, Ws[EDIM + e + t], bs[e + t])), 0.f);
            }
        }
        __half2* h = (__half2*)&areg;
        #pragma unroll
        for (int t = 0; t < 4; t++)
            h[t] = __floats2half2_rn(v[2 * t], v[2 * t + 1]);
    };
    auto store_A = [&](int buf) {
        *(uint4*)(As + buf * MPAD * A_ST + ar * A_ST + 8 * ac8) = areg;
    };

    // ---- B chunk: Wm -> regs (RN fp16) -----------------------------------
    uint4 breg[4];
    auto load_B = [&](int k0, int n0) {
        #pragma unroll
        for (int j = 0; j < 4; j++) {
            const int flat = tid + THREADS * j;
            const int r  = flat >> 5;        // 0..31
            const int c8 = flat & 31;        // group of 8 cols
            const float* src = Wm + (size_t)(k0 + r) * HDIM + n0 + 8 * c8;
            const float4 p0 = *(const float4*)(src);
            const float4 p1 = *(const float4*)(src + 4);
            __half2* h = (__half2*)&breg[j];
            h[0] = __floats2half2_rn(p0.x, p0.y);
            h[1] = __floats2half2_rn(p0.z, p0.w);
            h[2] = __floats2half2_rn(p1.x, p1.y);
            h[3] = __floats2half2_rn(p1.z, p1.w);
        }
    };
    auto store_B = [&](int buf) {
        #pragma unroll
        for (int j = 0; j < 4; j++) {
            const int flat = tid + THREADS * j;
            const int r  = flat >> 5;
            const int c8 = flat & 31;
            *(uint4*)(Bs + buf * KC * B_ST + r * B_ST + 8 * c8) = breg[j];
        }
    };

    for (int pass = 0; pass < 2; pass++) {
        const int n0 = pass * NP;

        wmma::fragment<wmma::accumulator, 16, 16, 16, float> acc[4][2];
        #pragma unroll
        for (int i = 0; i < 4; i++) {
            wmma::fill_fragment(acc[i][0], 0.0f);
            wmma::fill_fragment(acc[i][1], 0.0f);
        }

        // Prologue: chunk 0 -> buf 0
        load_A(0);
        load_B(0, n0);
        store_A(0);
        store_B(0);

        for (int i = 0; i < NCH; i++) {
            const int buf = i & 1;
            __syncthreads();   // chunk i visible; buf^1 readers done
            if (i + 1 < NCH) { // LDGs for chunk i+1 fly over the mma below
                load_A((i + 1) * KC);
                load_B((i + 1) * KC, n0);
            }

            const __half* Ab = As + buf * MPAD * A_ST;
            const __half* Bb = Bs + buf * KC * B_ST;
            #pragma unroll
            for (int kk = 0; kk < KC; kk += 16) {
                wmma::fragment<wmma::matrix_a, 16, 16, 16, __half,
                               wmma::row_major> fa[4];
                #pragma unroll
                for (int i2 = 0; i2 < 4; i2++)
                    wmma::load_matrix_sync(fa[i2], Ab + 16 * i2 * A_ST + kk, A_ST);
                #pragma unroll
                for (int j = 0; j < 2; j++) {
                    wmma::fragment<wmma::matrix_b, 16, 16, 16, __half,
                                   wmma::row_major> fb;
                    wmma::load_matrix_sync(fb, Bb + kk * B_ST + 32 * wid + 16 * j,
                                           B_ST);
                    #pragma unroll
                    for (int i2 = 0; i2 < 4; i2++)
                        wmma::mma_sync(acc[i2][j], fa[i2], fb, acc[i2][j]);
                }
            }
            if (i + 1 < NCH) {
                store_A(buf ^ 1);
                store_B(buf ^ 1);
            }
        }

        // ---- epilogue: strips in smem, column max, relu(+bm) --------------
        __syncthreads();
        float* strip = smemf + wid * (MPAD * S_ST);
        #pragma unroll
        for (int i = 0; i < 4; i++) {
            wmma::store_matrix_sync(strip + 16 * i * S_ST, acc[i][0],
                                    S_ST, wmma::mem_row_major);
            wmma::store_matrix_sync(strip + 16 * i * S_ST + 16, acc[i][1],
                                    S_ST, wmma::mem_row_major);
        }
        __syncthreads();
        {
            const int w = tid >> 5;
            const int c = tid & 31;
            const float* s = smemf + w * (MPAD * S_ST) + c;
            float m0 = s[0];
            float m1 = -3.4e38f, m2 = -3.4e38f, m3 = -3.4e38f;
            int r = 1;
            for (; r + 3 < cnt; r += 4) {
                m0 = fmaxf(m0, s[(r + 0) * S_ST]);
                m1 = fmaxf(m1, s[(r + 1) * S_ST]);
                m2 = fmaxf(m2, s[(r + 2) * S_ST]);
                m3 = fmaxf(m3, s[(r + 3) * S_ST]);
            }
            for (; r < cnt; r++)
                m0 = fmaxf(m0, s[r * S_ST]);
            const float mv = fmaxf(fmaxf(m0, m1), fmaxf(m2, m3));
            const int col = n0 + 32 * w + c;
            out[(size_t)g * HDIM + col] = fmaxf(mv + bm[col], 0.0f);
        }
        __syncthreads();   // strips read before next pass restages smem
    }
}

extern "C" void kernel_launch(void* const* d_in, const int* in_sizes, int n_in,
                              void* d_out, int out_size)
{
    const float* hist_enc = (const float*)d_in[0];
    const float* hist_pos = (const float*)d_in[1];
    const int*   sse      = (const int*)d_in[2];
    const float* Ws       = (const float*)d_in[3];
    const float* bs       = (const float*)d_in[4];
    const float* Wm       = (const float*)d_in[5];
    const float* bm       = (const float*)d_in[6];
    float* out            = (float*)d_out;

    const int num_groups = in_sizes[2] - 1;

    cudaFuncSetAttribute(pool_hidden_kernel,
                         cudaFuncAttributeMaxDynamicSharedMemorySize,
                         (int)SMEM_BYTES);

    pool_hidden_kernel<<<num_groups, THREADS, SMEM_BYTES>>>(
        hist_enc, hist_pos, sse, Ws, bs, Wm, bm, out);
}

// round 12
// speedup vs baseline: 6.4683x; 1.4185x over previous
#include <cuda_runtime.h>
#include <cuda_fp16.h>
#include <mma.h>
#include <cstdint>

using namespace nvcuda;

#define NMAX 102400
#define HDIM 512
#define EDIM 128
#define KTOT 640
#define MPAD 64          // one group (<=64 rows) per CTA
#define KC 64            // K chunk
#define NCH (KTOT / KC)  // 10 chunks per pass
#define NP 256           // N cols per pass (2 passes)
#define A_ST 72          // A row stride (halfs): 64 + 8
#define B_ST 264         // B row stride (halfs): 256 + 8
#define S_ST 36          // epilogue strip stride (floats)
#define THREADS 256      // 8 warps

#define A_BYTES (2 * MPAD * A_ST * 2)          // 18432
#define B_BYTES (2 * KC * B_ST * 2)            // 67584
#define SMEM_BYTES (A_BYTES + B_BYTES)         // 86016 (epilogue 73728 reuses)

// Precomputed fp16 operands (device-global scratch — allowed)
__device__ __half g_hin[(size_t)NMAX * KTOT];  // fused [hist_enc | emb]
__device__ __half g_wm[KTOT * HDIM];

__device__ __forceinline__ uint32_t smem_u32(const void* p) {
    uint32_t a;
    asm("{ .reg .u64 t; cvta.to.shared.u64 t, %1; cvt.u32.u64 %0, t; }" : "=r"(a) : "l"(p));
    return a;
}
__device__ __forceinline__ void cp_async16(uint32_t saddr, const void* gptr) {
    asm volatile("cp.async.cg.shared.global [%0], [%1], 16;" :: "r"(saddr), "l"(gptr));
}
#define CP_COMMIT() asm volatile("cp.async.commit_group;" ::: "memory")
#define CP_WAIT0()  asm volatile("cp.async.wait_group 0;" ::: "memory")

// ---- prekernel 1: Wm fp32 -> fp16 ------------------------------------------
__global__ void conv_wm_kernel(const float* __restrict__ Wm) {
    const int idx = blockIdx.x * 256 + threadIdx.x;   // 81920 float4s
    const float4 v = reinterpret_cast<const float4*>(Wm)[idx];
    __half2 h[2] = {__floats2half2_rn(v.x, v.y), __floats2half2_rn(v.z, v.w)};
    *reinterpret_cast<uint2*>(g_wm + 4 * (size_t)idx) = *reinterpret_cast<uint2*>(h);
}

// ---- prekernel 2: build fused H_in fp16 ------------------------------------
__global__ void build_hin_kernel(const float* __restrict__ hist_enc,
                                 const float* __restrict__ hist_pos,
                                 const int*   __restrict__ sse,
                                 const float* __restrict__ Ws,
                                 const float* __restrict__ bs) {
    const int g = blockIdx.x;
    const int start = sse[g];
    const int cnt = sse[g + 1] - start;
    const int tid = threadIdx.x;
    const float ax = hist_pos[2 * start + 0];
    const float ay = hist_pos[2 * start + 1];

    for (int idx = tid; idx < cnt * (HDIM / 4); idx += 256) {
        const int r = idx >> 7, c4 = idx & 127;
        const float4 v = *(const float4*)(hist_enc + (size_t)(start + r) * HDIM + 4 * c4);
        __half2 h[2] = {__floats2half2_rn(v.x, v.y), __floats2half2_rn(v.z, v.w)};
        *reinterpret_cast<uint2*>(g_hin + (size_t)(start + r) * KTOT + 4 * c4) =
            *reinterpret_cast<uint2*>(h);
    }
    for (int idx = tid; idx < cnt * (EDIM / 4); idx += 256) {
        const int r = idx >> 5, c4 = idx & 31;
        const int e = 4 * c4;
        const float rx = hist_pos[2 * (start + r) + 0] - ax;
        const float ry = hist_pos[2 * (start + r) + 1] - ay;
        const float v0 = fmaxf(fmaf(rx, Ws[e+0], fmaf(ry, Ws[EDIM+e+0], bs[e+0])), 0.f);
        const float v1 = fmaxf(fmaf(rx, Ws[e+1], fmaf(ry, Ws[EDIM+e+1], bs[e+1])), 0.f);
        const float v2 = fmaxf(fmaf(rx, Ws[e+2], fmaf(ry, Ws[EDIM+e+2], bs[e+2])), 0.f);
        const float v3 = fmaxf(fmaf(rx, Ws[e+3], fmaf(ry, Ws[EDIM+e+3], bs[e+3])), 0.f);
        __half2 h[2] = {__floats2half2_rn(v0, v1), __floats2half2_rn(v2, v3)};
        *reinterpret_cast<uint2*>(g_hin + (size_t)(start + r) * KTOT + HDIM + e) =
            *reinterpret_cast<uint2*>(h);
    }
}

// ---- main: fp16 GEMM + segment-max -----------------------------------------
__global__ __launch_bounds__(THREADS, 2)
void gemm_pool_kernel(const int* __restrict__ sse,
                      const float* __restrict__ bm,
                      float* __restrict__ out)
{
    extern __shared__ char sm[];
    __half* As = (__half*)sm;                  // [buf][64][A_ST]
    __half* Bs = (__half*)(sm + A_BYTES);      // [buf][KC][B_ST]
    float*  smf = (float*)sm;                  // epilogue strips

    const int g     = blockIdx.x;
    const int tid   = threadIdx.x;
    const int wid   = tid >> 5;
    const int start = sse[g];
    const int cnt   = sse[g + 1] - start;      // <= MPAD

    auto issue_A = [&](int k0, int buf) {
        const uint32_t sb = smem_u32(As + buf * MPAD * A_ST);
        const __half* gp = g_hin + (size_t)start * KTOT + k0;
        #pragma unroll
        for (int q = 0; q < 2; q++) {
            const int u = tid + THREADS * q;   // 512 units of 8 halfs
            const int r = u >> 3, c = u & 7;
            if (r < cnt)
                cp_async16(sb + (uint32_t)(r * A_ST + 8 * c) * 2,
                           gp + (size_t)r * KTOT + 8 * c);
        }
    };
    auto issue_B = [&](int k0, int n0, int buf) {
        const uint32_t sb = smem_u32(Bs + buf * KC * B_ST);
        const __half* gp = g_wm + (size_t)k0 * HDIM + n0;
        #pragma unroll
        for (int j = 0; j < 8; j++) {
            const int u = tid + THREADS * j;   // 2048 units of 8 halfs
            const int r = u >> 5, c = u & 31;  // row, 8-half column unit
            cp_async16(sb + (uint32_t)(r * B_ST + 8 * c) * 2,
                       gp + (size_t)r * HDIM + 8 * c);
        }
    };

    for (int pass = 0; pass < 2; pass++) {
        const int n0 = pass * NP;

        // zero A buffers (pad rows must be 0; cp.async writes only real rows)
        for (int idx = tid; idx < A_BYTES / 16; idx += THREADS)
            reinterpret_cast<uint4*>(As)[idx] = make_uint4(0, 0, 0, 0);
        __syncthreads();

        wmma::fragment<wmma::accumulator, 16, 16, 16, float> acc[4][2];
        #pragma unroll
        for (int i = 0; i < 4; i++) {
            wmma::fill_fragment(acc[i][0], 0.0f);
            wmma::fill_fragment(acc[i][1], 0.0f);
        }

        issue_A(0, 0);
        issue_B(0, n0, 0);
        CP_COMMIT();

        for (int i = 0; i < NCH; i++) {
            const int buf = i & 1;
            CP_WAIT0();
            __syncthreads();       // chunk i visible; buf^1 consumers done
            if (i + 1 < NCH) {     // copies for i+1 fly over the mma below
                issue_A((i + 1) * KC, buf ^ 1);
                issue_B((i + 1) * KC, n0, buf ^ 1);
                CP_COMMIT();
            }

            const __half* Ab = As + buf * MPAD * A_ST;
            const __half* Bb = Bs + buf * KC * B_ST;
            #pragma unroll
            for (int kk = 0; kk < KC; kk += 16) {
                wmma::fragment<wmma::matrix_a, 16, 16, 16, __half,
                               wmma::row_major> fa[4];
                #pragma unroll
                for (int i2 = 0; i2 < 4; i2++)
                    wmma::load_matrix_sync(fa[i2], Ab + 16 * i2 * A_ST + kk, A_ST);
                #pragma unroll
                for (int j = 0; j < 2; j++) {
                    wmma::fragment<wmma::matrix_b, 16, 16, 16, __half,
                                   wmma::row_major> fb;
                    wmma::load_matrix_sync(fb, Bb + kk * B_ST + 32 * wid + 16 * j,
                                           B_ST);
                    #pragma unroll
                    for (int i2 = 0; i2 < 4; i2++)
                        wmma::mma_sync(acc[i2][j], fa[i2], fb, acc[i2][j]);
                }
            }
        }

        // ---- epilogue: strips, column max over cnt rows, relu(+bm) --------
        __syncthreads();
        float* strip = smf + wid * (MPAD * S_ST);
        #pragma unroll
        for (int i = 0; i < 4; i++) {
            wmma::store_matrix_sync(strip + 16 * i * S_ST, acc[i][0],
                                    S_ST, wmma::mem_row_major);
            wmma::store_matrix_sync(strip + 16 * i * S_ST + 16, acc[i][1],
                                    S_ST, wmma::mem_row_major);
        }
        __syncthreads();
        {
            const int w = tid >> 5;
            const int c = tid & 31;
            const float* s = smf + w * (MPAD * S_ST) + c;
            float m0 = s[0];
            float m1 = -3.4e38f, m2 = -3.4e38f, m3 = -3.4e38f;
            int r = 1;
            for (; r + 3 < cnt; r += 4) {
                m0 = fmaxf(m0, s[(r + 0) * S_ST]);
                m1 = fmaxf(m1, s[(r + 1) * S_ST]);
                m2 = fmaxf(m2, s[(r + 2) * S_ST]);
                m3 = fmaxf(m3, s[(r + 3) * S_ST]);
            }
            for (; r < cnt; r++)
                m0 = fmaxf(m0, s[r * S_ST]);
            const float mv = fmaxf(fmaxf(m0, m1), fmaxf(m2, m3));
            const int col = n0 + 32 * w + c;
            out[(size_t)g * HDIM + col] = fmaxf(mv + bm[col], 0.0f);
        }
        __syncthreads();   // strips read before next pass rezeroes smem
    }
}

extern "C" void kernel_launch(void* const* d_in, const int* in_sizes, int n_in,
                              void* d_out, int out_size)
{
    const float* hist_enc = (const float*)d_in[0];
    const float* hist_pos = (const float*)d_in[1];
    const int*   sse      = (const int*)d_in[2];
    const float* Ws       = (const float*)d_in[3];
    const float* bs       = (const float*)d_in[4];
    const float* Wm       = (const float*)d_in[5];
    const float* bm       = (const float*)d_in[6];
    float* out            = (float*)d_out;

    const int num_groups = in_sizes[2] - 1;

    cudaFuncSetAttribute(gemm_pool_kernel,
                         cudaFuncAttributeMaxDynamicSharedMemorySize,
                         SMEM_BYTES);

    conv_wm_kernel<<<(KTOT * HDIM / 4) / 256, 256>>>(Wm);
    build_hin_kernel<<<num_groups, 256>>>(hist_enc, hist_pos, sse, Ws, bs);
    gemm_pool_kernel<<<num_groups, THREADS, SMEM_BYTES>>>(sse, bm, out);
}

// round 13
// speedup vs baseline: 6.7249x; 1.0397x over previous
#include <cuda_runtime.h>
#include <cuda_fp16.h>
#include <mma.h>
#include <cstdint>

using namespace nvcuda;

#define NMAX 102400
#define HDIM 512
#define EDIM 128
#define KTOT 640
#define MROWS 128        // dense M tile per CTA
#define KC 64            // K chunk
#define NCH (KTOT / KC)  // 10 chunks per pass
#define NP 128           // N cols per pass (4 passes)
#define A_ST 72          // A row stride (halfs): 64 + 8
#define B_ST 136         // B row stride (halfs): 128 + 8
#define S_ST 36          // epilogue strip stride (floats)
#define THREADS 256      // 8 warps: wm = wid>>2 (2), wn = wid&3 (4)

#define A_BYTES (2 * MROWS * A_ST * 2)         // 36864
#define B_BYTES (2 * KC * B_ST * 2)            // 34816
#define SMEM_BYTES (4 * MROWS * S_ST * 4)      // 73728 (>= A_BYTES+B_BYTES=71680)

// Precomputed fp16 operands (device-global scratch — allowed)
__device__ __half g_hin[(size_t)NMAX * KTOT];  // fused [hist_enc | emb]
__device__ __half g_wm[KTOT * HDIM];

__device__ __forceinline__ uint32_t smem_u32(const void* p) {
    uint32_t a;
    asm("{ .reg .u64 t; cvta.to.shared.u64 t, %1; cvt.u32.u64 %0, t; }" : "=r"(a) : "l"(p));
    return a;
}
__device__ __forceinline__ void cp_async16(uint32_t saddr, const void* gptr) {
    asm volatile("cp.async.cg.shared.global [%0], [%1], 16;" :: "r"(saddr), "l"(gptr));
}
#define CP_COMMIT() asm volatile("cp.async.commit_group;" ::: "memory")
#define CP_WAIT0()  asm volatile("cp.async.wait_group 0;" ::: "memory")

// ---- prekernel 0: zero the output (atomicMax target, relu output >= 0) -----
__global__ void init_out_kernel(float* __restrict__ out) {
    reinterpret_cast<float4*>(out)[blockIdx.x * 256 + threadIdx.x] =
        make_float4(0.f, 0.f, 0.f, 0.f);
}

// ---- prekernel 1: Wm fp32 -> fp16 ------------------------------------------
__global__ void conv_wm_kernel(const float* __restrict__ Wm) {
    const int idx = blockIdx.x * 256 + threadIdx.x;   // 81920 float4s
    const float4 v = reinterpret_cast<const float4*>(Wm)[idx];
    __half2 h[2] = {__floats2half2_rn(v.x, v.y), __floats2half2_rn(v.z, v.w)};
    *reinterpret_cast<uint2*>(g_wm + 4 * (size_t)idx) = *reinterpret_cast<uint2*>(h);
}

// ---- prekernel 2: build fused H_in fp16 ------------------------------------
__global__ void build_hin_kernel(const float* __restrict__ hist_enc,
                                 const float* __restrict__ hist_pos,
                                 const int*   __restrict__ sse,
                                 const float* __restrict__ Ws,
                                 const float* __restrict__ bs) {
    const int g = blockIdx.x;
    const int start = sse[g];
    const int cnt = sse[g + 1] - start;
    const int tid = threadIdx.x;
    const float ax = hist_pos[2 * start + 0];
    const float ay = hist_pos[2 * start + 1];

    for (int idx = tid; idx < cnt * (HDIM / 4); idx += 256) {
        const int r = idx >> 7, c4 = idx & 127;
        const float4 v = *(const float4*)(hist_enc + (size_t)(start + r) * HDIM + 4 * c4);
        __half2 h[2] = {__floats2half2_rn(v.x, v.y), __floats2half2_rn(v.z, v.w)};
        *reinterpret_cast<uint2*>(g_hin + (size_t)(start + r) * KTOT + 4 * c4) =
            *reinterpret_cast<uint2*>(h);
    }
    for (int idx = tid; idx < cnt * (EDIM / 4); idx += 256) {
        const int r = idx >> 5, c4 = idx & 31;
        const int e = 4 * c4;
        const float rx = hist_pos[2 * (start + r) + 0] - ax;
        const float ry = hist_pos[2 * (start + r) + 1] - ay;
        const float v0 = fmaxf(fmaf(rx, Ws[e+0], fmaf(ry, Ws[EDIM+e+0], bs[e+0])), 0.f);
        const float v1 = fmaxf(fmaf(rx, Ws[e+1], fmaf(ry, Ws[EDIM+e+1], bs[e+1])), 0.f);
        const float v2 = fmaxf(fmaf(rx, Ws[e+2], fmaf(ry, Ws[EDIM+e+2], bs[e+2])), 0.f);
        const float v3 = fmaxf(fmaf(rx, Ws[e+3], fmaf(ry, Ws[EDIM+e+3], bs[e+3])), 0.f);
        __half2 h[2] = {__floats2half2_rn(v0, v1), __floats2half2_rn(v2, v3)};
        *reinterpret_cast<uint2*>(g_hin + (size_t)(start + r) * KTOT + HDIM + e) =
            *reinterpret_cast<uint2*>(h);
    }
}

// ---- main: dense fp16 GEMM + tile-local segment max ------------------------
__global__ __launch_bounds__(THREADS, 2)
void gemm_pool_kernel(const int* __restrict__ sse,
                      const float* __restrict__ bm,
                      float* __restrict__ out,
                      int num_groups, int ntotal)
{
    extern __shared__ char sm[];
    __half* As = (__half*)sm;                  // [buf][128][A_ST]
    __half* Bs = (__half*)(sm + A_BYTES);      // [buf][KC][B_ST]
    float*  smf = (float*)sm;                  // epilogue strips

    const int tid  = threadIdx.x;
    const int wid  = tid >> 5;
    const int wm   = wid >> 2;                 // 0..1
    const int wn   = wid & 3;                  // 0..3
    const int row0 = blockIdx.x * MROWS;
    const int rmax = min(MROWS, ntotal - row0);

    // Group containing row0 (binary search; every thread, cached loads)
    int g0;
    {
        int lo = 0, hi = num_groups - 1;
        while (lo < hi) {
            const int mid = (lo + hi + 1) >> 1;
            if (sse[mid] <= row0) lo = mid; else hi = mid - 1;
        }
        g0 = lo;
    }

    auto issue_A = [&](int k0, int buf) {
        const uint32_t sb = smem_u32(As + buf * MROWS * A_ST);
        const __half* gp = g_hin + (size_t)row0 * KTOT + k0;
        #pragma unroll
        for (int q = 0; q < 4; q++) {
            const int u = tid + THREADS * q;   // 1024 units of 8 halfs
            const int r = u >> 3, c = u & 7;
            if (r < rmax)
                cp_async16(sb + (uint32_t)(r * A_ST + 8 * c) * 2,
                           gp + (size_t)r * KTOT + 8 * c);
        }
    };
    auto issue_B = [&](int k0, int n0, int buf) {
        const uint32_t sb = smem_u32(Bs + buf * KC * B_ST);
        const __half* gp = g_wm + (size_t)k0 * HDIM + n0;
        #pragma unroll
        for (int j = 0; j < 4; j++) {
            const int u = tid + THREADS * j;   // 1024 units of 8 halfs
            const int r = u >> 4, c = u & 15;
            cp_async16(sb + (uint32_t)(r * B_ST + 8 * c) * 2,
                       gp + (size_t)r * HDIM + 8 * c);
        }
    };

    for (int pass = 0; pass < 4; pass++) {
        const int n0 = pass * NP;

        if (rmax < MROWS) {   // pad rows must be zero (tail tile only)
            for (int idx = tid; idx < A_BYTES / 16; idx += THREADS)
                reinterpret_cast<uint4*>(As)[idx] = make_uint4(0, 0, 0, 0);
        }
        __syncthreads();      // strips of previous pass fully read; As ready

        wmma::fragment<wmma::accumulator, 16, 16, 16, float> acc[4][2];
        #pragma unroll
        for (int i = 0; i < 4; i++) {
            wmma::fill_fragment(acc[i][0], 0.0f);
            wmma::fill_fragment(acc[i][1], 0.0f);
        }

        issue_A(0, 0);
        issue_B(0, n0, 0);
        CP_COMMIT();

        for (int i = 0; i < NCH; i++) {
            const int buf = i & 1;
            CP_WAIT0();
            __syncthreads();       // chunk i visible; buf^1 consumers done
            if (i + 1 < NCH) {     // copies for i+1 fly over the mma below
                issue_A((i + 1) * KC, buf ^ 1);
                issue_B((i + 1) * KC, n0, buf ^ 1);
                CP_COMMIT();
            }

            const __half* Ab = As + buf * MROWS * A_ST;
            const __half* Bb = Bs + buf * KC * B_ST;
            #pragma unroll
            for (int kk = 0; kk < KC; kk += 16) {
                wmma::fragment<wmma::matrix_a, 16, 16, 16, __half,
                               wmma::row_major> fa[4];
                #pragma unroll
                for (int i2 = 0; i2 < 4; i2++)
                    wmma::load_matrix_sync(fa[i2],
                        Ab + (64 * wm + 16 * i2) * A_ST + kk, A_ST);
                #pragma unroll
                for (int j = 0; j < 2; j++) {
                    wmma::fragment<wmma::matrix_b, 16, 16, 16, __half,
                                   wmma::row_major> fb;
                    wmma::load_matrix_sync(fb,
                        Bb + kk * B_ST + 32 * wn + 16 * j, B_ST);
                    #pragma unroll
                    for (int i2 = 0; i2 < 4; i2++)
                        wmma::mma_sync(acc[i2][j], fa[i2], fb, acc[i2][j]);
                }
            }
        }

        // ---- epilogue: strips, per-segment column max, atomicMax ----------
        __syncthreads();   // mainloop smem dead; safe to overwrite with strips
        float* strip = smf + wn * (MROWS * S_ST);
        #pragma unroll
        for (int i = 0; i < 4; i++) {
            wmma::store_matrix_sync(strip + (64 * wm + 16 * i) * S_ST, acc[i][0],
                                    S_ST, wmma::mem_row_major);
            wmma::store_matrix_sync(strip + (64 * wm + 16 * i) * S_ST + 16,
                                    acc[i][1], S_ST, wmma::mem_row_major);
        }
        __syncthreads();

        if (tid < NP) {
            const int pcol = tid;
            const float* s = smf + (pcol >> 5) * (MROWS * S_ST) + (pcol & 31);
            const float bias = bm[n0 + pcol];
            int g = g0;
            int segend = min(sse[g + 1] - row0, rmax);
            float m = -3.4e38f;
            for (int r = 0; r < rmax; r++) {
                m = fmaxf(m, s[r * S_ST]);
                if (r + 1 == segend) {
                    const float val = fmaxf(m + bias, 0.f);
                    atomicMax((unsigned*)&out[(size_t)g * HDIM + n0 + pcol],
                              __float_as_uint(val));
                    g++;
                    segend = (g < num_groups) ? min(sse[g + 1] - row0, rmax)
                                              : rmax + 1;
                    m = -3.4e38f;
                }
            }
        }
        __syncthreads();   // strips read before next pass restages smem
    }
}

extern "C" void kernel_launch(void* const* d_in, const int* in_sizes, int n_in,
                              void* d_out, int out_size)
{
    const float* hist_enc = (const float*)d_in[0];
    const float* hist_pos = (const float*)d_in[1];
    const int*   sse      = (const int*)d_in[2];
    const float* Ws       = (const float*)d_in[3];
    const float* bs       = (const float*)d_in[4];
    const float* Wm       = (const float*)d_in[5];
    const float* bm       = (const float*)d_in[6];
    float* out            = (float*)d_out;

    const int num_groups = in_sizes[2] - 1;
    const int ntotal     = in_sizes[0] / HDIM;
    const int grid       = (ntotal + MROWS - 1) / MROWS;

    cudaFuncSetAttribute(gemm_pool_kernel,
                         cudaFuncAttributeMaxDynamicSharedMemorySize,
                         SMEM_BYTES);

    init_out_kernel<<<(out_size / 4 + 255) / 256, 256>>>(out);
    conv_wm_kernel<<<(KTOT * HDIM / 4) / 256, 256>>>(Wm);
    build_hin_kernel<<<num_groups, 256>>>(hist_enc, hist_pos, sse, Ws, bs);
    gemm_pool_kernel<<<grid, THREADS, SMEM_BYTES>>>(sse, bm, out,
                                                    num_groups, ntotal);
}